// round 12
// baseline (speedup 1.0000x reference)
#include <cuda_runtime.h>
#include <cuda_bf16.h>
#include <cstdint>

// Fused BN(affine) -> ReLU -> 2x2 AvgPool(stride 2) -> 1x1 Conv (channel GEMM)
// x:           [N=32, C_in=32, H=256, W=256] f32
// conv_weight: [C_in=32, C_out=16] f32 (row-major, w[c*16+d])
// bn_scale/bn_bias: [32] f32
// out:         [N=32, C_out=16, 128, 128] f32
//
// R11: test the read/write-interleave hypothesis. R9 skeleton (block tile =
// (n, 4 pooled rows), 8KB contiguous bulk-DMA read per channel into a depth-4
// mbarrier ring) + the block's 32KB output tile accumulated in SMEM and
// flushed at block end as 16 contiguous 2KB cp.async.bulk stores. Converts
// the chip-wide fine-grained read/write mix into mostly-pure-read phases with
// batched sequential write bursts.

#define C_IN  32
#define C_OUT 16
#define HIN   256
#define WIN   256
#define POUT  128
#define PLANE (POUT * POUT)     // 16384
#define CSTRIDE (HIN * WIN)     // 65536 floats
#define DEPTH 4
#define CHUNK 8192              // bytes per channel per block (8 rows x 1KB)

__device__ __forceinline__ unsigned long long pack_f32x2(float lo, float hi) {
    unsigned long long r;
    asm("mov.b64 %0, {%1, %2};" : "=l"(r) : "f"(lo), "f"(hi));
    return r;
}

__device__ __forceinline__ void fma_f32x2(unsigned long long& acc,
                                          unsigned long long a,
                                          unsigned long long b) {
    asm("fma.rn.f32x2 %0, %1, %2, %0;" : "+l"(acc) : "l"(a), "l"(b));
}

__device__ __forceinline__ unsigned int smem_u32(const void* p) {
    unsigned int a;
    asm("{ .reg .u64 t; cvta.to.shared.u64 t, %1; cvt.u32.u64 %0, t; }"
        : "=r"(a) : "l"(p));
    return a;
}

__device__ __forceinline__ void mbar_init(unsigned int mbar, unsigned int count) {
    asm volatile("mbarrier.init.shared.b64 [%0], %1;" :: "r"(mbar), "r"(count) : "memory");
}

__device__ __forceinline__ void mbar_expect_tx(unsigned int mbar, unsigned int bytes) {
    asm volatile("mbarrier.arrive.expect_tx.shared.b64 _, [%0], %1;"
                 :: "r"(mbar), "r"(bytes) : "memory");
}

__device__ __forceinline__ void bulk_load(unsigned int smem_dst, const void* gmem_src,
                                          unsigned int bytes, unsigned int mbar) {
    asm volatile(
        "cp.async.bulk.shared::cluster.global.mbarrier::complete_tx::bytes "
        "[%0], [%1], %2, [%3];"
        :: "r"(smem_dst), "l"(gmem_src), "r"(bytes), "r"(mbar) : "memory");
}

__device__ __forceinline__ void bulk_store(void* gmem_dst, unsigned int smem_src,
                                           unsigned int bytes) {
    asm volatile(
        "cp.async.bulk.global.shared::cta.bulk_group [%0], [%1], %2;"
        :: "l"(gmem_dst), "r"(smem_src), "r"(bytes) : "memory");
}

__device__ __forceinline__ void mbar_wait(unsigned int mbar, unsigned int parity) {
    asm volatile(
        "{\n\t"
        ".reg .pred P;\n\t"
        "WL_%=:\n\t"
        "mbarrier.try_wait.parity.acquire.cta.shared::cta.b64 P, [%0], %1, 0x989680;\n\t"
        "@P bra.uni WD_%=;\n\t"
        "bra.uni WL_%=;\n\t"
        "WD_%=:\n\t"
        "}"
        :: "r"(mbar), "r"(parity) : "memory");
}

__global__ __launch_bounds__(256, 3) void fused_bn_relu_pool_conv(
    const float* __restrict__ x,
    const float* __restrict__ wmat,
    const float* __restrict__ scale,
    const float* __restrict__ bias,
    float* __restrict__ out)
{
    __shared__ alignas(128) char  stage[DEPTH][CHUNK];     // 32 KB read ring
    __shared__ alignas(16)  float s_out[C_OUT][4][POUT];   // 32 KB output tile
    __shared__ float2 s_w2[C_IN * C_OUT];                  // {0.25w,0.25w}, 4 KB
    __shared__ float  s_sc[C_IN];
    __shared__ float  s_bi[C_IN];
    __shared__ alignas(8) unsigned long long mbar_store[DEPTH];

    const int tid = threadIdx.x;
    for (int i = tid; i < C_IN * C_OUT; i += 256) {
        const float w = 0.25f * wmat[i];
        s_w2[i] = make_float2(w, w);
    }
    if (tid < C_IN) { s_sc[tid] = scale[tid]; s_bi[tid] = bias[tid]; }

    const unsigned int mb0 = smem_u32(&mbar_store[0]);
    if (tid < DEPTH) mbar_init(mb0 + tid * 8u, 1u);
    __syncthreads();   // barriers + weights visible before any bulk copy

    // Block tile: image n, pooled-row group hg (4 pooled rows = 8 input rows)
    const int n  = blockIdx.x >> 5;
    const int hg = blockIdx.x & 31;
    const float* src0 = x + (size_t)n * C_IN * CSTRIDE + (size_t)(8 * hg) * WIN;

    const unsigned int st0 = smem_u32(&stage[0][0]);

    // Prologue: fill all DEPTH slots (channels 0..3), phase 0
    if (tid == 0) {
#pragma unroll
        for (int k = 0; k < DEPTH; k++) {
            mbar_expect_tx(mb0 + (unsigned)k * 8u, CHUNK);
            bulk_load(st0 + (unsigned)k * CHUNK, src0 + (size_t)k * CSTRIDE,
                      CHUNK, mb0 + (unsigned)k * 8u);
        }
    }

    // Thread mapping within tile: h2l = pooled row 0..3, wq = pooled col pair
    const int h2l = tid >> 6;          // 0..3
    const int wq  = tid & 63;          // pooled cols {2wq, 2wq+1}
    const unsigned int rd0 = (unsigned)(2 * h2l) * 1024u + (unsigned)wq * 16u;

    unsigned long long acc[C_OUT];
#pragma unroll
    for (int d = 0; d < C_OUT; d++) acc[d] = 0ULL;

#pragma unroll
    for (int c = 0; c < C_IN; c++) {
        const int s  = c & (DEPTH - 1);
        const unsigned int ph = (unsigned)(c >> 2) & 1u;
        mbar_wait(mb0 + (unsigned)s * 8u, ph);

        const float4 r0 = *reinterpret_cast<const float4*>(&stage[s][rd0]);
        const float4 r1 = *reinterpret_cast<const float4*>(&stage[s][rd0 + 1024u]);
        const float sc = s_sc[c];
        const float bi = s_bi[c];

        // BN + ReLU on all 8 taps
        const float v0 = fmaxf(fmaf(r0.x, sc, bi), 0.0f);
        const float v1 = fmaxf(fmaf(r0.y, sc, bi), 0.0f);
        const float v2 = fmaxf(fmaf(r0.z, sc, bi), 0.0f);
        const float v3 = fmaxf(fmaf(r0.w, sc, bi), 0.0f);
        const float u0 = fmaxf(fmaf(r1.x, sc, bi), 0.0f);
        const float u1 = fmaxf(fmaf(r1.y, sc, bi), 0.0f);
        const float u2 = fmaxf(fmaf(r1.z, sc, bi), 0.0f);
        const float u3 = fmaxf(fmaf(r1.w, sc, bi), 0.0f);

        // 2x2 pool sums (the *0.25 is folded into the weights)
        const float p0 = (v0 + v1) + (u0 + u1);
        const float p1 = (v2 + v3) + (u2 + u3);
        const unsigned long long p = pack_f32x2(p0, p1);

        const unsigned long long* w2 =
            reinterpret_cast<const unsigned long long*>(&s_w2[c * C_OUT]);
#pragma unroll
        for (int d = 0; d < C_OUT; d++) {
            fma_f32x2(acc[d], p, w2[d]);
        }

        // All threads done reading slot s -> safe to overwrite with channel c+4
        __syncthreads();
        if (tid == 0 && c + DEPTH < C_IN) {
            mbar_expect_tx(mb0 + (unsigned)s * 8u, CHUNK);
            bulk_load(st0 + (unsigned)s * CHUNK,
                      src0 + (size_t)(c + DEPTH) * CSTRIDE,
                      CHUNK, mb0 + (unsigned)s * 8u);
        }
    }

    // Stage the output tile in SMEM (batched write phase)
#pragma unroll
    for (int d = 0; d < C_OUT; d++) {
        *reinterpret_cast<float2*>(&s_out[d][h2l][2 * wq]) =
            *reinterpret_cast<const float2*>(&acc[d]);
    }
    __syncthreads();
    asm volatile("fence.proxy.async.shared::cta;" ::: "memory");

    // Flush: 16 contiguous 2KB bulk stores (one per output plane slab).
    // out[n][d][4*hg .. 4*hg+3][0..127] is 2048B contiguous.
    if (tid < C_OUT) {
        float* dst = out + ((size_t)n * C_OUT + tid) * PLANE + (size_t)(4 * hg) * POUT;
        bulk_store(dst, smem_u32(&s_out[tid][0][0]), 4 * POUT * sizeof(float));
        asm volatile("cp.async.bulk.commit_group;" ::: "memory");
        asm volatile("cp.async.bulk.wait_group.read 0;" ::: "memory");
    }
}

extern "C" void kernel_launch(void* const* d_in, const int* in_sizes, int n_in,
                              void* d_out, int out_size)
{
    const float* x     = (const float*)d_in[0];
    const float* wmat  = (const float*)d_in[1];
    const float* scale = (const float*)d_in[2];
    const float* bias  = (const float*)d_in[3];
    float* out         = (float*)d_out;

    // 32 images x 32 row-groups = 1024 blocks x 256 threads
    fused_bn_relu_pool_conv<<<1024, 256>>>(x, wmat, scale, bias, out);
}

// round 13
// speedup vs baseline: 1.1182x; 1.1182x over previous
#include <cuda_runtime.h>
#include <cuda_bf16.h>
#include <cstdint>

// Fused BN(affine) -> ReLU -> 2x2 AvgPool(stride 2) -> 1x1 Conv (channel GEMM)
// x:           [N=32, C_in=32, H=256, W=256] f32
// conv_weight: [C_in=32, C_out=16] f32 (row-major, w[c*16+d])
// bn_scale/bn_bias: [32] f32
// out:         [N=32, C_out=16, 128, 128] f32
//
// R12 (final): R5 structure exactly -- per-thread cp.async ring depth 5, two
// pooled pixels per thread, float4 row-pair loads, packed f32x2 GEMM, no
// in-loop barriers -- plus streaming (evict-first) st.global.cs stores from
// R10, which gave the best steady-state wall time. Twelve-round ledger:
// seven structural designs all plateau at 5.1-5.9 TB/s; this variant sits at
// the plateau top (~74% DRAM active, ~95% of the practical mixed-stream
// ceiling). HBM-bound; tensor pipes are irrelevant for this op.

#define C_IN  32
#define C_OUT 16
#define HIN   256
#define WIN   256
#define POUT  128
#define CSTRIDE (HIN * WIN)   // 65536
#define PIPE  5

__device__ __forceinline__ unsigned long long pack_f32x2(float lo, float hi) {
    unsigned long long r;
    asm("mov.b64 %0, {%1, %2};" : "=l"(r) : "f"(lo), "f"(hi));
    return r;
}

__device__ __forceinline__ void fma_f32x2(unsigned long long& acc,
                                          unsigned long long a,
                                          unsigned long long b) {
    asm("fma.rn.f32x2 %0, %1, %2, %0;" : "+l"(acc) : "l"(a), "l"(b));
}

__device__ __forceinline__ void cp16(unsigned int smem_dst, const float* gmem_src) {
    asm volatile("cp.async.cg.shared.global.L2::256B [%0], [%1], 16;"
                 :: "r"(smem_dst), "l"(gmem_src));
}

__device__ __forceinline__ void cp_commit() {
    asm volatile("cp.async.commit_group;");
}

template <int N>
__device__ __forceinline__ void cp_wait() {
    asm volatile("cp.async.wait_group %0;" :: "n"(N));
}

__device__ __forceinline__ unsigned int smem_u32(const void* p) {
    unsigned int a;
    asm("{ .reg .u64 t; cvta.to.shared.u64 t, %1; cvt.u32.u64 %0, t; }"
        : "=r"(a) : "l"(p));
    return a;
}

__device__ __forceinline__ void stg_cs_v2(float* p, unsigned long long v) {
    asm volatile("st.global.cs.v2.f32 [%0], {%1, %2};"
                 :: "l"(p),
                    "f"(__uint_as_float((unsigned int)(v & 0xffffffffu))),
                    "f"(__uint_as_float((unsigned int)(v >> 32)))
                 : "memory");
}

__global__ __launch_bounds__(256, 4) void fused_bn_relu_pool_conv(
    const float* __restrict__ x,
    const float* __restrict__ wmat,
    const float* __restrict__ scale,
    const float* __restrict__ bias,
    float* __restrict__ out)
{
    // Per-thread staging ring: stage[k][r][tid] (r = row 0/1 of the 2x2 window)
    __shared__ float4 stage[PIPE][2][256];              // 40 KB
    __shared__ float2 s_w2[C_IN * C_OUT];               // {0.25w, 0.25w}, 4 KB
    __shared__ float  s_sc[C_IN];
    __shared__ float  s_bi[C_IN];

    const int tid = threadIdx.x;
    for (int i = tid; i < C_IN * C_OUT; i += 256) {
        const float w = 0.25f * wmat[i];
        s_w2[i] = make_float2(w, w);
    }
    if (tid < C_IN) { s_sc[tid] = scale[tid]; s_bi[tid] = bias[tid]; }
    __syncthreads();

    // Thread mapping: image n, pooled row h2, pooled columns {2*wq, 2*wq+1}
    const int g   = blockIdx.x * 256 + tid;
    const int n   = g >> 13;          // 8192 thread-slots per image
    const int rem = g & 8191;
    const int h2  = rem >> 6;         // 0..127
    const int wq  = rem & 63;         // 0..63

    const float* base = x + ((size_t)n * C_IN * HIN + 2 * h2) * WIN + 4 * wq;

    // smem addresses for this thread's ring slots; slot (k,r) at st0+(k*2+r)*4096
    const unsigned int st0 = smem_u32(&stage[0][0][tid]);

    // Prime PIPE-1 channel groups
#pragma unroll
    for (int k = 0; k < PIPE - 1; k++) {
        cp16(st0 + (unsigned int)(k * 2 + 0) * 4096u, base + (size_t)k * CSTRIDE);
        cp16(st0 + (unsigned int)(k * 2 + 1) * 4096u, base + (size_t)k * CSTRIDE + WIN);
        cp_commit();
    }

    unsigned long long acc[C_OUT];
#pragma unroll
    for (int d = 0; d < C_OUT; d++) acc[d] = 0ULL;

#pragma unroll
    for (int c = 0; c < C_IN; c++) {
        // Issue the load PIPE-1 channels ahead, then wait for channel c.
        if (c + PIPE - 1 < C_IN) {
            const int ck = c + PIPE - 1;
            const int k  = ck % PIPE;
            cp16(st0 + (unsigned int)(k * 2 + 0) * 4096u, base + (size_t)ck * CSTRIDE);
            cp16(st0 + (unsigned int)(k * 2 + 1) * 4096u, base + (size_t)ck * CSTRIDE + WIN);
            cp_commit();
            cp_wait<PIPE - 1>();   // channels <= c complete (FIFO)
        } else {
            switch (C_IN - 1 - c) {
                case 3: cp_wait<3>(); break;
                case 2: cp_wait<2>(); break;
                case 1: cp_wait<1>(); break;
                default: cp_wait<0>(); break;
            }
        }

        const int k = c % PIPE;
        const float4 r0 = stage[k][0][tid];
        const float4 r1 = stage[k][1][tid];
        const float sc = s_sc[c];
        const float bi = s_bi[c];

        // BN + ReLU on all 8 taps
        const float v0 = fmaxf(fmaf(r0.x, sc, bi), 0.0f);
        const float v1 = fmaxf(fmaf(r0.y, sc, bi), 0.0f);
        const float v2 = fmaxf(fmaf(r0.z, sc, bi), 0.0f);
        const float v3 = fmaxf(fmaf(r0.w, sc, bi), 0.0f);
        const float u0 = fmaxf(fmaf(r1.x, sc, bi), 0.0f);
        const float u1 = fmaxf(fmaf(r1.y, sc, bi), 0.0f);
        const float u2 = fmaxf(fmaf(r1.z, sc, bi), 0.0f);
        const float u3 = fmaxf(fmaf(r1.w, sc, bi), 0.0f);

        // 2x2 pool sums (the *0.25 is folded into the weights)
        const float p0 = (v0 + v1) + (u0 + u1);
        const float p1 = (v2 + v3) + (u2 + u3);
        const unsigned long long p = pack_f32x2(p0, p1);

        const unsigned long long* w2 =
            reinterpret_cast<const unsigned long long*>(&s_w2[c * C_OUT]);
#pragma unroll
        for (int d = 0; d < C_OUT; d++) {
            fma_f32x2(acc[d], p, w2[d]);
        }
    }

    // Output: out[n][d][h2][2*wq .. 2*wq+1]; acc bits are exactly {p0,p1}.
    // Streaming (evict-first) stores: output is never re-read by this kernel,
    // and keeping it out of L2 helps the next graph replay's read stream.
    float* o = out + (size_t)n * C_OUT * (POUT * POUT) + h2 * POUT + 2 * wq;
#pragma unroll
    for (int d = 0; d < C_OUT; d++) {
        stg_cs_v2(o + (size_t)d * (POUT * POUT), acc[d]);
    }
}

extern "C" void kernel_launch(void* const* d_in, const int* in_sizes, int n_in,
                              void* d_out, int out_size)
{
    const float* x     = (const float*)d_in[0];
    const float* wmat  = (const float*)d_in[1];
    const float* scale = (const float*)d_in[2];
    const float* bias  = (const float*)d_in[3];
    float* out         = (float*)d_out;

    // 32 images * 128 pooled rows * 64 column-pairs = 262144 threads
    fused_bn_relu_pool_conv<<<1024, 256>>>(x, wmat, scale, bias, out);
}